// round 8
// baseline (speedup 1.0000x reference)
#include <cuda_runtime.h>
#include <cuda_bf16.h>
#include <cstdint>

// ============================================================================
// ProxyISA loss — bf16x3 split GEMM (fp32-accurate cos) + fused epilogue.
// cos = inputs @ l2norm(proxies)^T [1024 x 16384], E=512.
// Split: x = hi + lo (bf16); cos ~= AhBh + AhBl + AlBh (fp32 accum).
//
// Two GEMM backends, selected at compile time per ptxas target:
//   - sm_103a (arch-specific): tcgen05 SS MMA, TMEM accum, mbarrier-pipelined
//   - sm_103 family fallback : mma.sync.m16n8k16 (validated round-4 path)
// Both deterministic; host code identical.
// ============================================================================

#if defined(__CUDA_ARCH__) && \
    (defined(__CUDA_ARCH_FEAT_SM103_ALL) || \
     (defined(__CUDA_ARCH_SPECIFIC__) && (__CUDA_ARCH_SPECIFIC__ == 1030)))
#define HAS_TC 1
#else
#define HAS_TC 0
#endif

#define ALPHA 32.0f
#define MRG   0.1f
#define KCON  1.0f
#define LAM   0.1f

#define Bsz 1024
#define Esz 512
#define Csz 16384

#define CPB   128
#define NBLK  (Csz / CPB)        // 128 CTAs
#define NTIL  (Bsz / 128)        // 8 M-tiles
#define NCH_T (Esz / 64)         // 8 K64 chunks (tcgen05 path)
#define NTHR  256

// idesc: f32 accum, bf16 A, bf16 B, N=128, M=128 (cta_group::1)
#define IDESC ((1u<<4) | (1u<<7) | (1u<<10) | (16u<<17) | (8u<<24))

// ---- device scratch ----
__device__ __nv_bfloat16 g_Ah[Bsz * Esz];
__device__ __nv_bfloat16 g_Al[Bsz * Esz];
__device__ __nv_bfloat16 g_Bh[Csz * Esz];
__device__ __nv_bfloat16 g_Bl[Csz * Esz];
__device__ float2        g_cls[Csz];
__device__ int           g_cnt[Csz];
__device__ float4        g_part[NBLK];

// ---- tcgen05-path smem layout (byte offsets) ----
#define T_OFF_BH   0                 // 8 subtiles [128 x 64 bf16] = 131072
#define T_OFF_CH   131072            // 2 x {Ah 16K | Al 16K | Bl 16K}
#define T_CH_SZ    49152
#define T_OFF_TP   229376            // tmem ptr
#define T_OFF_MB   229384            // mbar[2] + tile mbar
#define T_OFF_OUT  229408            // outS[128]
#define T_OFF_INV  229920            // invE[128]
#define T_OFF_ACCP 230432            // accP[128][3]
#define T_OFF_ACCW T_OFF_CH          // accW[4][128][3] aliased into chunk buf
#define T_OFF_RED  (T_OFF_CH + 6144) // red[128][4]     aliased into chunk buf
#define SMEM_MAIN  231968

// ---- fallback (mma.sync) smem layout ----
#define F_A_STR  72
#define F_BH_STR 520
#define F_OFF_BH 0
#define F_SZ_BH  (128 * F_BH_STR * 2)        // 133120
#define F_OFF_AH (F_OFF_BH + F_SZ_BH)
#define F_SZ_A   (128 * F_A_STR * 2)         // 18432
#define F_OFF_AL (F_OFF_AH + F_SZ_A)
#define F_OFF_BL (F_OFF_AL + F_SZ_A)
#define F_OFF_F  (F_OFF_BL + F_SZ_A)         // floats region (fits < SMEM_MAIN)

// ---------------------------------------------------------------------------
__device__ __forceinline__ uint32_t smem_u32(const void* p) {
    uint32_t a;
    asm("{ .reg .u64 t; cvta.to.shared.u64 t, %1; cvt.u32.u64 %0, t; }"
        : "=r"(a) : "l"(p));
    return a;
}
__device__ __forceinline__ void split2(float x, __nv_bfloat16& h, __nv_bfloat16& l) {
    h = __float2bfloat16_rn(x);
    l = __float2bfloat16_rn(x - __bfloat162float(h));
}
// Fast e^x on FMA/ALU pipes (no MUFU); |x| <= ~40 here; rel err ~3e-7.
__device__ __forceinline__ float fexp(float x) {
    const float L2E = 1.4426950408889634f;
    float z  = fmaf(x, L2E, 12582912.0f);
    int   n  = __float_as_int(z);
    float xi = z - 12582912.0f;
    float f  = fmaf(x, L2E, -xi);
    float p  = 0.0013333558f;
    p = fmaf(p, f, 0.0096181291f);
    p = fmaf(p, f, 0.0555041087f);
    p = fmaf(p, f, 0.2402265070f);
    p = fmaf(p, f, 0.6931471806f);
    p = fmaf(p, f, 1.0f);
    return __int_as_float(__float_as_int(p) + (n << 23));
}

#if HAS_TC
// ---- tcgen05 helpers (compiled only on arch-specific pass) ----
__device__ __forceinline__ bool elect_one() {
    uint32_t p;
    asm volatile("{\n\t.reg .pred P;\n\telect.sync _|P, 0xFFFFFFFF;\n\t"
                 "selp.b32 %0, 1, 0, P;\n\t}" : "=r"(p));
    return p != 0;
}
__device__ __forceinline__ uint64_t make_desc(uint32_t addr) {
    return ((uint64_t)2 << 61) | ((uint64_t)1 << 46) | ((uint64_t)64 << 32) |
           ((uint64_t)1 << 16) | ((uint64_t)(addr >> 4) & 0x3FFF);
}
#define SW128(o) ((o) ^ (((o) >> 3) & 0x70))
__device__ __forceinline__ void mma_f16_ss(uint32_t d, uint64_t ad, uint64_t bd,
                                           uint32_t en) {
    asm volatile(
        "{\n\t.reg .pred p;\n\tsetp.ne.u32 p, %4, 0;\n\t"
        "tcgen05.mma.cta_group::1.kind::f16 [%0], %1, %2, %3, {%5,%5,%5,%5}, p;\n\t}"
        :: "r"(d), "l"(ad), "l"(bd), "r"(IDESC), "r"(en), "r"(0u) : "memory");
}
__device__ __forceinline__ void commit_to(uint32_t mbar) {
    asm volatile(
        "tcgen05.commit.cta_group::1.mbarrier::arrive::one.shared::cluster.b64 [%0];"
        :: "r"(mbar) : "memory");
}
#define TMEM_LD_X32(r, addr) \
    asm volatile("tcgen05.ld.sync.aligned.32x32b.x32.b32 " \
        "{%0,%1,%2,%3,%4,%5,%6,%7,%8,%9,%10,%11,%12,%13,%14,%15," \
        "%16,%17,%18,%19,%20,%21,%22,%23,%24,%25,%26,%27,%28,%29,%30,%31}, [%32];" \
        : "=r"((r)[0]),"=r"((r)[1]),"=r"((r)[2]),"=r"((r)[3]),"=r"((r)[4]), \
          "=r"((r)[5]),"=r"((r)[6]),"=r"((r)[7]),"=r"((r)[8]),"=r"((r)[9]), \
          "=r"((r)[10]),"=r"((r)[11]),"=r"((r)[12]),"=r"((r)[13]),"=r"((r)[14]), \
          "=r"((r)[15]),"=r"((r)[16]),"=r"((r)[17]),"=r"((r)[18]),"=r"((r)[19]), \
          "=r"((r)[20]),"=r"((r)[21]),"=r"((r)[22]),"=r"((r)[23]),"=r"((r)[24]), \
          "=r"((r)[25]),"=r"((r)[26]),"=r"((r)[27]),"=r"((r)[28]),"=r"((r)[29]), \
          "=r"((r)[30]),"=r"((r)[31]) : "r"(addr))
#endif  // HAS_TC

// mbarrier helpers are family-portable (sm_90+)
__device__ __forceinline__ void mbar_init(uint32_t a, uint32_t c) {
    asm volatile("mbarrier.init.shared.b64 [%0], %1;" :: "r"(a), "r"(c) : "memory");
}
__device__ __forceinline__ void mbar_wait(uint32_t a, uint32_t parity) {
    uint32_t done;
    asm volatile(
        "{\n\t.reg .pred p;\n\t"
        "mbarrier.try_wait.parity.acquire.cta.shared::cta.b64 p, [%1], %2;\n\t"
        "selp.b32 %0, 1, 0, p;\n\t}"
        : "=r"(done) : "r"(a), "r"(parity) : "memory");
    if (!done) {
        asm volatile(
            "{\n\t.reg .pred P1;\n\t"
            "W%=:\n\t"
            "mbarrier.try_wait.parity.acquire.cta.shared::cta.b64 P1, [%0], %1, 0x989680;\n\t"
            "@P1 bra.uni D%=;\n\t"
            "bra.uni W%=;\n\t"
            "D%=:\n\t}"
            :: "r"(a), "r"(parity) : "memory");
    }
}

#if !HAS_TC
// ---- mma.sync helpers (fallback) ----
__device__ __forceinline__ void ldmA4(uint32_t* a, uint32_t addr) {
    asm volatile("ldmatrix.sync.aligned.m8n8.x4.shared.b16 {%0,%1,%2,%3}, [%4];"
                 : "=r"(a[0]), "=r"(a[1]), "=r"(a[2]), "=r"(a[3]) : "r"(addr));
}
__device__ __forceinline__ void ldmB2(uint32_t& b0, uint32_t& b1, uint32_t addr) {
    asm volatile("ldmatrix.sync.aligned.m8n8.x2.shared.b16 {%0,%1}, [%2];"
                 : "=r"(b0), "=r"(b1) : "r"(addr));
}
__device__ __forceinline__ void mma16816(float* d, const uint32_t* a,
                                         uint32_t b0, uint32_t b1) {
    asm volatile(
        "mma.sync.aligned.m16n8k16.row.col.f32.bf16.bf16.f32 "
        "{%0,%1,%2,%3}, {%4,%5,%6,%7}, {%8,%9}, {%0,%1,%2,%3};"
        : "+f"(d[0]), "+f"(d[1]), "+f"(d[2]), "+f"(d[3])
        : "r"(a[0]), "r"(a[1]), "r"(a[2]), "r"(a[3]), "r"(b0), "r"(b1));
}
#endif

// ---------------------------------------------------------------------------
__global__ void prep_inputs_kernel(const float* __restrict__ in) {
    int i = blockIdx.x * blockDim.x + threadIdx.x;
    const float4* in4 = (const float4*)in;
    for (int k = i; k < (Bsz * Esz) / 4; k += 65536) {
        float4 v = in4[k];
        __nv_bfloat16 h0, l0, h1, l1, h2, l2, h3, l3;
        split2(v.x, h0, l0); split2(v.y, h1, l1);
        split2(v.z, h2, l2); split2(v.w, h3, l3);
        ((__nv_bfloat162*)g_Ah)[k * 2 + 0] = __nv_bfloat162(h0, h1);
        ((__nv_bfloat162*)g_Ah)[k * 2 + 1] = __nv_bfloat162(h2, h3);
        ((__nv_bfloat162*)g_Al)[k * 2 + 0] = __nv_bfloat162(l0, l1);
        ((__nv_bfloat162*)g_Al)[k * 2 + 1] = __nv_bfloat162(l2, l3);
    }
}

__global__ void prep_proxies_kernel(const float* __restrict__ proxies,
                                    const float* __restrict__ eff,
                                    const float* __restrict__ ls) {
    __shared__ float ws[4];
    int row = blockIdx.x;
    int tid = threadIdx.x;                                    // 128
    float4 v = ((const float4*)proxies)[(size_t)row * 128 + tid];
    float s = v.x * v.x + v.y * v.y + v.z * v.z + v.w * v.w;
    #pragma unroll
    for (int d = 16; d > 0; d >>= 1) s += __shfl_xor_sync(0xffffffffu, s, d);
    if ((tid & 31) == 0) ws[tid >> 5] = s;
    __syncthreads();
    float rn = rsqrtf(ws[0] + ws[1] + ws[2] + ws[3] + 1e-12f);
    size_t base = (size_t)row * 256 + tid * 2;
    __nv_bfloat16 h0, l0, h1, l1, h2, l2, h3, l3;
    split2(v.x * rn, h0, l0); split2(v.y * rn, h1, l1);
    split2(v.z * rn, h2, l2); split2(v.w * rn, h3, l3);
    ((__nv_bfloat162*)g_Bh)[base + 0] = __nv_bfloat162(h0, h1);
    ((__nv_bfloat162*)g_Bh)[base + 1] = __nv_bfloat162(h2, h3);
    ((__nv_bfloat162*)g_Bl)[base + 0] = __nv_bfloat162(l0, l1);
    ((__nv_bfloat162*)g_Bl)[base + 1] = __nv_bfloat162(l2, l3);
    if (tid == 0) {
        float e = eff[row], l = ls[row];
        float wb = 1.0f / (1.0f + log1pf(e));
        float eta = (1.0f + KCON * (1.0f - l)) * wb + LAM;
        g_cls[row] = make_float2(l - eta, 1.0f / fmaxf(1.0f, e));
        g_cnt[row] = 0;
    }
}

__global__ void prep_count_kernel(const int* __restrict__ targets) {
    int i = blockIdx.x * blockDim.x + threadIdx.x;
    if (i < Bsz) atomicAdd(&g_cnt[targets[i]], 1);
}

// ---------------------------------------------------------------------------
__global__ void __launch_bounds__(NTHR, 1)
main_kernel(const int* __restrict__ targets) {
    extern __shared__ char smem[];
    const int tid  = threadIdx.x;
    const int lane = tid & 31;
    const int w    = tid >> 5;           // 8 warps
    const int cb   = blockIdx.x;
    const uint32_t sbase = smem_u32(smem);

#if HAS_TC
    // ======================= tcgen05 path (sm_103a) ========================
    float* outS = (float*)(smem + T_OFF_OUT);
    float* invE = (float*)(smem + T_OFF_INV);
    float* accP = (float*)(smem + T_OFF_ACCP);
    float* accW = (float*)(smem + T_OFF_ACCW);
    float* red  = (float*)(smem + T_OFF_RED);

    if (w == 0) {
        asm volatile("tcgen05.alloc.cta_group::1.sync.aligned.shared::cta.b32 [%0], %1;"
                     :: "r"(sbase + T_OFF_TP), "r"(256u) : "memory");
    }
    if (tid == 0) {
        mbar_init(sbase + T_OFF_MB + 0, 1);
        mbar_init(sbase + T_OFF_MB + 8, 1);
        mbar_init(sbase + T_OFF_MB + 16, 1);
    }
    __syncthreads();
    uint32_t tmem_base;
    asm volatile("ld.shared.b32 %0, [%1];" : "=r"(tmem_base) : "r"(sbase + T_OFF_TP));

    // resident B_hi: 8 subtiles [128 rows x 64 bf16], SW128
    for (int i = tid; i < 8192; i += NTHR) {
        int kb = i >> 10, r = (i >> 3) & 127, v = i & 7;
        uint4 d = *(const uint4*)&g_Bh[(size_t)(cb * 128 + r) * Esz + kb * 64 + v * 8];
        *(uint4*)(smem + T_OFF_BH + kb * 16384 + SW128(r * 128 + v * 16)) = d;
    }
    if (tid < 128) {
        float2 p = g_cls[cb * 128 + tid];
        outS[tid] = p.x;
        invE[tid] = p.y;
        accP[tid * 3 + 0] = 0.0f;
        accP[tid * 3 + 1] = 0.0f;
        accP[tid * 3 + 2] = 0.0f;
    }
    __syncthreads();

    int ph[2] = {0, 0};

    for (int tile = 0; tile < NTIL; ++tile) {
        for (int ch = 0; ch < NCH_T; ++ch) {
            const int gi = tile * NCH_T + ch;
            const int b  = gi & 1;
            const uint32_t bufo = T_OFF_CH + b * T_CH_SZ;

            if (gi >= 2) { mbar_wait(sbase + T_OFF_MB + b * 8, ph[b]); ph[b] ^= 1; }
            __syncthreads();

            for (int i = tid; i < 1024; i += NTHR) {
                int r = i >> 3, v = i & 7;
                size_t ga = (size_t)(tile * 128 + r) * Esz + ch * 64 + v * 8;
                uint32_t so = SW128(r * 128 + v * 16);
                *(uint4*)(smem + bufo + so)         = *(const uint4*)&g_Ah[ga];
                *(uint4*)(smem + bufo + 16384 + so) = *(const uint4*)&g_Al[ga];
                size_t gb = (size_t)(cb * 128 + r) * Esz + ch * 64 + v * 8;
                *(uint4*)(smem + bufo + 32768 + so) = *(const uint4*)&g_Bl[gb];
            }
            asm volatile("fence.proxy.async.shared::cta;" ::: "memory");
            __syncthreads();

            if (w == 0 && elect_one()) {
                uint64_t dAh = make_desc(sbase + bufo);
                uint64_t dAl = make_desc(sbase + bufo + 16384);
                uint64_t dBl = make_desc(sbase + bufo + 32768);
                uint64_t dBh = make_desc(sbase + T_OFF_BH + ch * 16384);
                #pragma unroll
                for (int ks = 0; ks < 4; ++ks) {
                    uint32_t en0 = (ch > 0 || ks > 0) ? 1u : 0u;
                    mma_f16_ss(tmem_base, dAh + ks * 2, dBh + ks * 2, en0);
                    mma_f16_ss(tmem_base, dAh + ks * 2, dBl + ks * 2, 1u);
                    mma_f16_ss(tmem_base, dAl + ks * 2, dBh + ks * 2, 1u);
                }
                commit_to(sbase + T_OFF_MB + b * 8);
                if (ch == NCH_T - 1) commit_to(sbase + T_OFF_MB + 16);
            }
        }

        mbar_wait(sbase + T_OFF_MB + 16, tile & 1);
        asm volatile("tcgen05.fence::after_thread_sync;" ::: "memory");
        __syncthreads();   // chunk buffers now free to alias as accW/red

        const int g = w & 3;          // TMEM subpartition (rows g*32..g*32+31)
        const int q = w >> 2;         // column half
        const int row = g * 32 + lane;
        const int tg = targets[tile * 128 + row];

        #pragma unroll
        for (int half = 0; half < 2; ++half) {
            uint32_t dr[32];
            TMEM_LD_X32(dr, tmem_base + q * 64 + half * 32);
            asm volatile("tcgen05.wait::ld.sync.aligned;" ::: "memory");

            #pragma unroll
            for (int grp = 0; grp < 4; ++grp) {
                const int cb8 = q * 64 + half * 32 + grp * 8;
                float sP[8], sN[8], sM[8];
                #pragma unroll
                for (int j = 0; j < 8; ++j) {
                    int c = cb8 + j;
                    float cosv = __uint_as_float(dr[grp * 8 + j]);
                    float o = outS[c], e = invE[c];
                    if (tg == cb * 128 + c) {
                        sP[j] = fexp(ALPHA * (MRG - cosv));
                        sN[j] = 0.0f; sM[j] = 0.0f;
                    } else {
                        float m = (cosv < o) ? e : 1.0f;
                        sP[j] = 0.0f;
                        sN[j] = fexp(ALPHA * (cosv + MRG) * m);
                        sM[j] = m;
                    }
                }
                #pragma unroll
                for (int d = 1; d < 32; d <<= 1) {
                    #pragma unroll
                    for (int j = 0; j < 8; ++j) {
                        sP[j] += __shfl_xor_sync(0xffffffffu, sP[j], d);
                        sN[j] += __shfl_xor_sync(0xffffffffu, sN[j], d);
                        sM[j] += __shfl_xor_sync(0xffffffffu, sM[j], d);
                    }
                }
                #pragma unroll
                for (int j = 0; j < 8; ++j) {
                    if (lane == j) {
                        float* wp = &accW[(g * 128 + cb8 + j) * 3];
                        wp[0] = sP[j]; wp[1] = sN[j]; wp[2] = sM[j];
                    }
                }
            }
        }
        asm volatile("tcgen05.fence::before_thread_sync;" ::: "memory");
        __syncthreads();

        if (tid < 128) {
            float s0 = 0, s1 = 0, s2 = 0;
            #pragma unroll
            for (int gg = 0; gg < 4; ++gg) {
                const float* wp = &accW[(gg * 128 + tid) * 3];
                s0 += wp[0]; s1 += wp[1]; s2 += wp[2];
            }
            accP[tid * 3 + 0] += s0;
            accP[tid * 3 + 1] += s1;
            accP[tid * 3 + 2] += s2;
        }
        __syncthreads();
    }

    if (tid < 128) {
        float sP = accP[tid * 3 + 0];
        float sN = accP[tid * 3 + 1];
        float sM = accP[tid * 3 + 2];
        int cnt = g_cnt[cb * 128 + tid];
        int Ncnt = Bsz - cnt;
        red[tid * 4 + 0] = log1pf(sP);
        red[tid * 4 + 1] = log1pf(sN);
        red[tid * 4 + 2] = (Ncnt > 0) ? sM / (float)Ncnt : 0.0f;
        red[tid * 4 + 3] = (cnt > 0) ? 1.0f : 0.0f;
    }
    __syncthreads();
    if (tid == 0) {
        float a = 0, b2 = 0, c = 0, d = 0;
        for (int i = 0; i < 128; i++) {
            a  += red[i * 4 + 0];
            b2 += red[i * 4 + 1];
            c  += red[i * 4 + 2];
            d  += red[i * 4 + 3];
        }
        g_part[cb] = make_float4(a, b2, c, d);
    }
    __syncthreads();
    if (w == 0) {
        asm volatile("tcgen05.relinquish_alloc_permit.cta_group::1.sync.aligned;");
        asm volatile("tcgen05.dealloc.cta_group::1.sync.aligned.b32 %0, %1;"
                     :: "r"(tmem_base), "r"(256u));
    }

#else
    // ================== mma.sync fallback (sm_103 family) ==================
    __nv_bfloat16* Bh = (__nv_bfloat16*)(smem + F_OFF_BH);
    __nv_bfloat16* Ah = (__nv_bfloat16*)(smem + F_OFF_AH);
    __nv_bfloat16* Al = (__nv_bfloat16*)(smem + F_OFF_AL);
    __nv_bfloat16* Bl = (__nv_bfloat16*)(smem + F_OFF_BL);
    float* outS = (float*)(smem + F_OFF_F);
    float* invE = outS + 128;
    float* accW = invE + 128;            // [4][128][3]
    float* accP = accW + 4 * 128 * 3;    // [128][3]
    float* red  = accP + 128 * 3;        // [128][4]
    int*   tgts = (int*)(red + 128 * 4); // [128]

    const int mw   = w >> 1;
    const int nwId = w & 1;
    const uint32_t bh_base = sbase + F_OFF_BH;
    const uint32_t ah_base = sbase + F_OFF_AH;
    const uint32_t al_base = sbase + F_OFF_AL;
    const uint32_t bl_base = sbase + F_OFF_BL;

    for (int i = tid; i < 128 * 64; i += NTHR) {
        int r = i >> 6, s = i & 63;
        uint4 v = *(const uint4*)&g_Bh[(size_t)(cb * 128 + r) * Esz + s * 8];
        *(uint4*)&Bh[r * F_BH_STR + s * 8] = v;
    }
    if (tid < 128) {
        float2 p = g_cls[cb * 128 + tid];
        outS[tid] = p.x;
        invE[tid] = p.y;
        accP[tid * 3 + 0] = 0.0f;
        accP[tid * 3 + 1] = 0.0f;
        accP[tid * 3 + 2] = 0.0f;
    }
    __syncthreads();

    for (int tile = 0; tile < NTIL; ++tile) {
        if (tid < 128) tgts[tid] = targets[tile * 128 + tid];

        float acc[2][8][4];
        #pragma unroll
        for (int mf = 0; mf < 2; mf++)
            #pragma unroll
            for (int nf = 0; nf < 8; nf++)
                #pragma unroll
                for (int qq = 0; qq < 4; qq++) acc[mf][nf][qq] = 0.0f;

        for (int ch = 0; ch < 8; ++ch) {
            __syncthreads();
            for (int i = tid; i < 128 * 8; i += NTHR) {
                int r = i >> 3, s = i & 7;
                size_t ga = (size_t)(tile * 128 + r) * Esz + ch * 64 + s * 8;
                *(uint4*)&Ah[r * F_A_STR + s * 8] = *(const uint4*)&g_Ah[ga];
                *(uint4*)&Al[r * F_A_STR + s * 8] = *(const uint4*)&g_Al[ga];
                size_t gb = (size_t)(cb * 128 + r) * Esz + ch * 64 + s * 8;
                *(uint4*)&Bl[r * F_A_STR + s * 8] = *(const uint4*)&g_Bl[gb];
            }
            __syncthreads();

            #pragma unroll
            for (int ks = 0; ks < 4; ++ks) {
                const int kb = ks * 16;
                uint32_t ah[2][4], al[2][4];
                {
                    int sub = lane >> 3, r = lane & 7;
                    int rofs = ((sub & 1) ? 8 : 0) + r;
                    int cofs = kb + ((sub >> 1) ? 8 : 0);
                    #pragma unroll
                    for (int mf = 0; mf < 2; mf++) {
                        int row = mw * 32 + mf * 16 + rofs;
                        ldmA4(ah[mf], ah_base + (row * F_A_STR + cofs) * 2);
                        ldmA4(al[mf], al_base + (row * F_A_STR + cofs) * 2);
                    }
                }
                int subb = (lane >> 3) & 1, rb = lane & 7;
                #pragma unroll
                for (int nf = 0; nf < 8; nf++) {
                    int row = nwId * 64 + nf * 8 + rb;
                    uint32_t bh0, bh1, bl0, bl1;
                    ldmB2(bh0, bh1,
                          bh_base + (row * F_BH_STR + ch * 64 + kb + subb * 8) * 2);
                    ldmB2(bl0, bl1,
                          bl_base + (row * F_A_STR + kb + subb * 8) * 2);
                    #pragma unroll
                    for (int mf = 0; mf < 2; mf++) {
                        mma16816(acc[mf][nf], ah[mf], bh0, bh1);
                        mma16816(acc[mf][nf], ah[mf], bl0, bl1);
                        mma16816(acc[mf][nf], al[mf], bh0, bh1);
                    }
                }
            }
        }

        #pragma unroll
        for (int nf = 0; nf < 8; nf++) {
            int cl0 = nwId * 64 + nf * 8 + 2 * (lane & 3);
            float o0 = outS[cl0], o1 = outS[cl0 + 1];
            float e0 = invE[cl0], e1 = invE[cl0 + 1];
            int gc0 = cb * 128 + cl0, gc1 = gc0 + 1;
            float sP0 = 0, sN0 = 0, sM0 = 0, sP1 = 0, sN1 = 0, sM1 = 0;
            #pragma unroll
            for (int mf = 0; mf < 2; mf++) {
                #pragma unroll
                for (int h = 0; h < 2; h++) {
                    int row = mw * 32 + (lane >> 2) + h * 8 + mf * 16;
                    int tg = tgts[row];
                    float c0v = acc[mf][nf][h * 2 + 0];
                    float c1v = acc[mf][nf][h * 2 + 1];
                    if (tg == gc0) {
                        sP0 += fexp(ALPHA * (MRG - c0v));
                    } else {
                        float m = (c0v < o0) ? e0 : 1.0f;
                        sN0 += fexp(ALPHA * (c0v + MRG) * m);
                        sM0 += m;
                    }
                    if (tg == gc1) {
                        sP1 += fexp(ALPHA * (MRG - c1v));
                    } else {
                        float m = (c1v < o1) ? e1 : 1.0f;
                        sN1 += fexp(ALPHA * (c1v + MRG) * m);
                        sM1 += m;
                    }
                }
            }
            #pragma unroll
            for (int d = 4; d < 32; d <<= 1) {
                sP0 += __shfl_xor_sync(0xffffffffu, sP0, d);
                sN0 += __shfl_xor_sync(0xffffffffu, sN0, d);
                sM0 += __shfl_xor_sync(0xffffffffu, sM0, d);
                sP1 += __shfl_xor_sync(0xffffffffu, sP1, d);
                sN1 += __shfl_xor_sync(0xffffffffu, sN1, d);
                sM1 += __shfl_xor_sync(0xffffffffu, sM1, d);
            }
            if (lane < 4) {
                int c = nwId * 64 + nf * 8 + 2 * lane;
                float* wp = &accW[(mw * 128 + c) * 3];
                wp[0] = sP0; wp[1] = sN0; wp[2] = sM0;
                wp[3] = sP1; wp[4] = sN1; wp[5] = sM1;
            }
        }
        __syncthreads();
        if (tid < 128) {
            float s0 = 0, s1 = 0, s2 = 0;
            #pragma unroll
            for (int g = 0; g < 4; g++) {
                const float* wp = &accW[(g * 128 + tid) * 3];
                s0 += wp[0]; s1 += wp[1]; s2 += wp[2];
            }
            accP[tid * 3 + 0] += s0;
            accP[tid * 3 + 1] += s1;
            accP[tid * 3 + 2] += s2;
        }
        __syncthreads();
    }

    if (tid < 128) {
        float sP = accP[tid * 3 + 0];
        float sN = accP[tid * 3 + 1];
        float sM = accP[tid * 3 + 2];
        int cnt = g_cnt[cb * 128 + tid];
        int Ncnt = Bsz - cnt;
        red[tid * 4 + 0] = log1pf(sP);
        red[tid * 4 + 1] = log1pf(sN);
        red[tid * 4 + 2] = (Ncnt > 0) ? sM / (float)Ncnt : 0.0f;
        red[tid * 4 + 3] = (cnt > 0) ? 1.0f : 0.0f;
    }
    __syncthreads();
    if (tid == 0) {
        float a = 0, b = 0, c = 0, d = 0;
        for (int i = 0; i < 128; i++) {
            a += red[i * 4 + 0];
            b += red[i * 4 + 1];
            c += red[i * 4 + 2];
            d += red[i * 4 + 3];
        }
        g_part[cb] = make_float4(a, b, c, d);
    }
#endif
}

__global__ void finalize_kernel(float* __restrict__ out) {
    if (threadIdx.x == 0) {
        float p = 0, n = 0, nw = 0, pw = 0;
        for (int i = 0; i < NBLK; i++) {
            float4 v = g_part[i];
            p += v.x; n += v.y; nw += v.z; pw += v.w;
        }
        out[0] = p / pw + n / nw;
    }
}

// ---------------------------------------------------------------------------
extern "C" void kernel_launch(void* const* d_in, const int* in_sizes, int n_in,
                              void* d_out, int out_size) {
    const float* inputs  = (const float*)d_in[0];
    const int*   targets = (const int*)d_in[1];
    const float* proxies = (const float*)d_in[2];
    const float* eff     = (const float*)d_in[3];
    const float* ls      = (const float*)d_in[4];
    float* out = (float*)d_out;

    cudaFuncSetAttribute(main_kernel,
                         cudaFuncAttributeMaxDynamicSharedMemorySize, SMEM_MAIN);

    prep_inputs_kernel<<<256, 256>>>(inputs);
    prep_proxies_kernel<<<Csz, 128>>>(proxies, eff, ls);
    prep_count_kernel<<<4, 256>>>(targets);
    main_kernel<<<NBLK, NTHR, SMEM_MAIN>>>(targets);
    finalize_kernel<<<1, 32>>>(out);
}